// round 8
// baseline (speedup 1.0000x reference)
#include <cuda_runtime.h>
#include <cstdint>

// Problem constants (fixed by the reference: B=32, M=4, D=196608)
constexpr int B_     = 32;
constexpr int M_     = 4;
constexpr int D_     = 196608;
constexpr int D4_    = D_ / 4;           // 49152 float4 per row
constexpr int BPG    = 9;                // blocks per group -> grid 288 (~2 blocks/SM)
constexpr int TPB    = 256;
constexpr int NWARP  = TPB / 32;
constexpr int NSLOT  = 36;               // 10 + 10 + 16
constexpr int GRID   = B_ * BPG;

constexpr int NROWS       = 8;           // 4 st rows + 4 sr rows
constexpr int CHUNK4      = 256;         // float4 per row per chunk (== TPB)
constexpr int CHUNK_BYTES = CHUNK4 * 16; // 4096 B per row per chunk
constexpr int STAGE4      = NROWS * CHUNK4;
constexpr int STAGE_BYTES = NROWS * CHUNK_BYTES;   // 32 KB
constexpr int STAGES      = 3;
constexpr int NCHUNK      = D4_ / CHUNK4;          // 192 chunks per group
constexpr int SMEM_BYTES  = STAGES * STAGE_BYTES + 64;  // + mbarrier region

static_assert(NCHUNK * CHUNK4 == D4_, "chunking must be exact");

// Static scratch: fixed-order reductions (deterministic; atomics only on int counters)
__device__ float        g_partials[GRID * NSLOT];
__device__ float        g_loss[B_];
__device__ unsigned int g_gcount[B_];    // per-group blocks-done counters (self-reset)
__device__ unsigned int g_fcount = 0;    // groups-finalized counter (self-reset)

__device__ __forceinline__ unsigned smem_u32(const void* p) {
    return (unsigned)__cvta_generic_to_shared(p);
}

__device__ __forceinline__ void mbar_init(unsigned mb, unsigned count) {
    asm volatile("mbarrier.init.shared::cta.b64 [%0], %1;" :: "r"(mb), "r"(count) : "memory");
}

__device__ __forceinline__ void mbar_expect_tx(unsigned mb, unsigned bytes) {
    asm volatile("mbarrier.arrive.expect_tx.shared::cta.b64 _, [%0], %1;"
                 :: "r"(mb), "r"(bytes) : "memory");
}

__device__ __forceinline__ void bulk_ld(unsigned dst_smem, const void* src_gmem,
                                        unsigned bytes, unsigned mb) {
    asm volatile("cp.async.bulk.shared::cluster.global.mbarrier::complete_tx::bytes "
                 "[%0], [%1], %2, [%3];"
                 :: "r"(dst_smem), "l"(src_gmem), "r"(bytes), "r"(mb) : "memory");
}

__device__ __forceinline__ void mbar_wait(unsigned mb, unsigned parity) {
    asm volatile(
        "{\n\t"
        ".reg .pred P;\n\t"
        "W%=:\n\t"
        "mbarrier.try_wait.parity.shared::cta.b64 P, [%0], %1;\n\t"
        "@!P bra W%=;\n\t"
        "}"
        :: "r"(mb), "r"(parity) : "memory");
}

__device__ __forceinline__ void accum36(float acc[NSLOT], const float4 a[4], const float4 c[4]) {
#pragma unroll
    for (int v = 0; v < 4; v++) {
        float x[4], y[4];
#pragma unroll
        for (int i = 0; i < 4; i++) {
            x[i] = reinterpret_cast<const float*>(&a[i])[v];
            y[i] = reinterpret_cast<const float*>(&c[i])[v];
        }
        int s = 0;
#pragma unroll
        for (int i = 0; i < 4; i++)
#pragma unroll
            for (int j = i; j < 4; j++) { acc[s] = fmaf(x[i], x[j], acc[s]); s++; }
#pragma unroll
        for (int i = 0; i < 4; i++)
#pragma unroll
            for (int j = i; j < 4; j++) { acc[s] = fmaf(y[i], y[j], acc[s]); s++; }
#pragma unroll
        for (int i = 0; i < 4; i++)
#pragma unroll
            for (int j = 0; j < 4; j++) { acc[s] = fmaf(x[i], y[j], acc[s]); s++; }
    }
}

__global__ __launch_bounds__(TPB) void mmd_fused(const float* __restrict__ st,
                                                 const float* __restrict__ sr,
                                                 const float* __restrict__ wt,
                                                 const float* __restrict__ wtout,
                                                 float* __restrict__ out) {
    extern __shared__ unsigned char smem_raw[];
    float4*   buf  = reinterpret_cast<float4*>(smem_raw);
    uint64_t* mbar = reinterpret_cast<uint64_t*>(smem_raw + STAGES * STAGE_BYTES);

    const int blk  = blockIdx.x;
    const int b    = blk / BPG;
    const int sub  = blk - b * BPG;
    const int tid  = threadIdx.x;
    const int warp = tid >> 5;
    const int lane = tid & 31;

    // Row base pointers: rows 0-3 = st group b, rows 4-7 = sr group b.
    const float4* rows[NROWS];
#pragma unroll
    for (int r = 0; r < 4; r++) {
        rows[r]     = reinterpret_cast<const float4*>(st) + (size_t)(b * M_ + r) * D4_;
        rows[4 + r] = reinterpret_cast<const float4*>(sr) + (size_t)(b * M_ + r) * D4_;
    }

    unsigned mb[STAGES];
#pragma unroll
    for (int s = 0; s < STAGES; s++) mb[s] = smem_u32(&mbar[s]);

    if (tid == 0) {
#pragma unroll
        for (int s = 0; s < STAGES; s++) mbar_init(mb[s], 1);
    }
    __syncthreads();

    // This block's chunks: c = sub + i*BPG, i = 0..n-1
    const int n = (NCHUNK - sub + BPG - 1) / BPG;   // 21 or 22

    // Prologue: fill the pipeline
    if (tid == 0) {
        const int pro = (n < STAGES) ? n : STAGES;
        for (int p = 0; p < pro; p++) {
            const int c = sub + p * BPG;
            mbar_expect_tx(mb[p], STAGE_BYTES);
            unsigned dst = smem_u32(buf + p * STAGE4);
#pragma unroll
            for (int r = 0; r < NROWS; r++)
                bulk_ld(dst + r * CHUNK_BYTES, rows[r] + (size_t)c * CHUNK4, CHUNK_BYTES, mb[p]);
        }
    }

    float acc[NSLOT];
#pragma unroll
    for (int s = 0; s < NSLOT; s++) acc[s] = 0.0f;

    int stage = 0, phase = 0;
    for (int i = 0; i < n; i++) {
        mbar_wait(mb[stage], phase);

        const float4* sb = buf + stage * STAGE4;
        float4 a[4], c4[4];
#pragma unroll
        for (int r = 0; r < 4; r++) {
            a[r]  = sb[r * CHUNK4 + tid];
            c4[r] = sb[(4 + r) * CHUNK4 + tid];
        }
        accum36(acc, a, c4);

        __syncthreads();   // all threads done reading this stage

        if (tid == 0 && i + STAGES < n) {
            const int c = sub + (i + STAGES) * BPG;
            mbar_expect_tx(mb[stage], STAGE_BYTES);
            unsigned dst = smem_u32(buf + stage * STAGE4);
#pragma unroll
            for (int r = 0; r < NROWS; r++)
                bulk_ld(dst + r * CHUNK_BYTES, rows[r] + (size_t)c * CHUNK4, CHUNK_BYTES, mb[stage]);
        }

        if (++stage == STAGES) { stage = 0; phase ^= 1; }
    }

    // Warp tree reduction of all 36 accumulators
#pragma unroll
    for (int s = 0; s < NSLOT; s++) {
        float v = acc[s];
        v += __shfl_down_sync(0xffffffffu, v, 16);
        v += __shfl_down_sync(0xffffffffu, v, 8);
        v += __shfl_down_sync(0xffffffffu, v, 4);
        v += __shfl_down_sync(0xffffffffu, v, 2);
        v += __shfl_down_sync(0xffffffffu, v, 1);
        acc[s] = v;
    }

    __shared__ float sm[NWARP][NSLOT];
    if (lane == 0) {
#pragma unroll
        for (int s = 0; s < NSLOT; s++) sm[warp][s] = acc[s];
    }
    __syncthreads();

    if (tid < NSLOT) {
        float t = 0.0f;
#pragma unroll
        for (int w = 0; w < NWARP; w++) t += sm[w][tid];
        g_partials[blk * NSLOT + tid] = t;
    }

    // ---- per-group last-block election (finalize overlaps other groups' streaming) ----
    __shared__ unsigned int s_isGroupLast;
    __threadfence();
    __syncthreads();
    if (tid == 0) {
        unsigned int old = atomicAdd(&g_gcount[b], 1u);
        s_isGroupLast = (old == (unsigned int)(BPG - 1)) ? 1u : 0u;
    }
    __syncthreads();
    if (!s_isGroupLast) return;
    __threadfence();

    // ---- group finalize: sum BPG partials per slot (fixed order) ----
    __shared__ float G[NSLOT];
    if (tid < NSLOT) {
        const float* p = &g_partials[(b * BPG) * NSLOT + tid];
        float t = 0.0f;
#pragma unroll
        for (int kb = 0; kb < BPG; kb++) t += p[kb * NSLOT];
        G[tid] = t;
    }
    __syncthreads();

    if (warp == 0) {
        const float w    = wt[b];
        const float invD = 1.0f / (float)D_;   // sigma = 1
        float contrib = 0.0f;
        if (lane < 16) {
            const int i = lane >> 2;
            const int j = lane & 3;
            auto tri = [](int r, int cc) {     // r <= cc
                const int off[4] = {0, 4, 7, 9};
                return off[r] + (cc - r);
            };
            const int ij = (i <= j) ? tri(i, j) : tri(j, i);
            const float gst_ii = G[tri(i, i)];
            const float gst_jj = G[tri(j, j)];
            const float gsr_ii = G[10 + tri(i, i)];
            const float gsr_jj = G[10 + tri(j, j)];
            const float gst_ij = G[ij];
            const float gsr_ij = G[10 + ij];
            const float c_ij   = G[20 + i * 4 + j];

            auto kterm = [&](float dii, float djj, float dij) {
                float d2 = fmaxf(dii + djj - 2.0f * dij, 1e-12f);
                float e  = -sqrtf(d2) * invD * w;
                e = fminf(fmaxf(e, -1e6f), 0.0f);
                return expf(e);
            };
            contrib = kterm(gst_ii, gst_jj, gst_ij)
                    + kterm(gsr_ii, gsr_jj, gsr_ij)
                    - 2.0f * kterm(gst_ii, gsr_jj, c_ij);
        }
        contrib += __shfl_down_sync(0xffffffffu, contrib, 8);
        contrib += __shfl_down_sync(0xffffffffu, contrib, 4);
        contrib += __shfl_down_sync(0xffffffffu, contrib, 2);
        contrib += __shfl_down_sync(0xffffffffu, contrib, 1);
        if (lane == 0) {
            g_loss[b] = wtout[b] * (contrib * (1.0f / 16.0f));
            g_gcount[b] = 0;               // reset for next graph replay
        }
    }

    // ---- global last-group election ----
    __shared__ unsigned int s_isGlobalLast;
    __threadfence();
    __syncthreads();
    if (tid == 0) {
        unsigned int old = atomicAdd(&g_fcount, 1u);
        s_isGlobalLast = (old == (unsigned int)(B_ - 1)) ? 1u : 0u;
    }
    __syncthreads();
    if (!s_isGlobalLast) return;
    __threadfence();

    if (warp == 0) {
        float v = g_loss[lane];
        v += __shfl_down_sync(0xffffffffu, v, 16);
        v += __shfl_down_sync(0xffffffffu, v, 8);
        v += __shfl_down_sync(0xffffffffu, v, 4);
        v += __shfl_down_sync(0xffffffffu, v, 2);
        v += __shfl_down_sync(0xffffffffu, v, 1);
        if (lane == 0) {
            out[0] = v * (1.0f / (float)B_);
            g_fcount = 0;                  // reset for next graph replay
            __threadfence();
        }
    }
}

extern "C" void kernel_launch(void* const* d_in, const int* in_sizes, int n_in,
                              void* d_out, int out_size) {
    const float* f_st  = (const float*)d_in[0];
    const float* f_sr  = (const float*)d_in[1];
    const float* wt    = (const float*)d_in[2];
    const float* wtout = (const float*)d_in[3];
    float* out = (float*)d_out;

    static bool attr_done = false;
    if (!attr_done) {
        cudaFuncSetAttribute(mmd_fused, cudaFuncAttributeMaxDynamicSharedMemorySize, SMEM_BYTES);
        attr_done = true;
    }
    mmd_fused<<<GRID, TPB, SMEM_BYTES>>>(f_st, f_sr, wt, wtout, out);
}